// round 8
// baseline (speedup 1.0000x reference)
#include <cuda_runtime.h>
#include <cuda_bf16.h>
#include <math.h>

// Problem constants (fixed by the reference)
#define BQ 2
#define TT 2048
#define CC 1024
#define HH 16
#define DD 64
#define MM (BQ*TT)   // 4096 rows

// Scratch (device globals: allocation-free rule)
__device__ float g_q[(size_t)MM*CC];
__device__ float g_k[(size_t)MM*CC];
__device__ float g_v[(size_t)MM*CC];
__device__ float g_Q[(size_t)MM*CC];   // [B,H,T,D], rope applied
__device__ float g_K[(size_t)MM*CC];   // [B,H,T,D], rope applied
__device__ float g_V[(size_t)MM*CC];   // [B,H,T,D]
__device__ float g_att[(size_t)MM*CC]; // [B,T,C] attention output

__device__ __forceinline__ void cp16(void* dst, const void* src) {
    unsigned d = (unsigned)__cvta_generic_to_shared(dst);
    asm volatile("cp.async.cg.shared.global [%0], [%1], 16;\n" :: "r"(d), "l"(src));
}
#define CP_COMMIT() asm volatile("cp.async.commit_group;\n")
#define CP_WAIT(n)  asm volatile("cp.async.wait_group %0;\n" :: "n"(n))

__device__ __forceinline__ void mma_tf32(float c[4], const unsigned a[4],
                                         unsigned b0, unsigned b1) {
    asm volatile(
        "mma.sync.aligned.m16n8k8.row.col.f32.tf32.tf32.f32 "
        "{%0,%1,%2,%3}, {%4,%5,%6,%7}, {%8,%9}, {%0,%1,%2,%3};\n"
        : "+f"(c[0]), "+f"(c[1]), "+f"(c[2]), "+f"(c[3])
        : "r"(a[0]), "r"(a[1]), "r"(a[2]), "r"(a[3]), "r"(b0), "r"(b1));
}
#define CVT_TF32(x) asm volatile("cvt.rna.tf32.f32 %0, %0;\n" : "+r"(x))

// ---------------------------------------------------------------------------
// TF32 tensor-core GEMM, 2-stage pipelined: C = A @ W + bias (M=4096,N=K=1024)
// ---------------------------------------------------------------------------
#define GBM 128
#define GBN 128
#define GBK 32
#define AS_STRIDE 36
#define BS_STRIDE 136
#define G_ASZ (GBM * AS_STRIDE)            // 4608 floats
#define G_BSZ (GBK * BS_STRIDE)            // 4352 floats
#define G_STAGE (G_ASZ + G_BSZ)            // 8960 floats
#define G_SMEM_BYTES (2 * G_STAGE * 4)     // 71680 B

__global__ __launch_bounds__(256, 2) void gemm_tf32(
    const float* __restrict__ Aext, const float* __restrict__ W,
    const float* __restrict__ bias, float* __restrict__ Cext,
    int srcFlag, int dstFlag)
{
    const float* A = srcFlag ? g_att : Aext;
    float* C = (dstFlag == 0) ? g_q : (dstFlag == 1) ? g_k
             : (dstFlag == 2) ? g_v : Cext;

    extern __shared__ __align__(16) float gsm[];

    const int tid  = threadIdx.x;
    const int lane = tid & 31;
    const int w    = tid >> 5;
    const int wr   = w >> 2;
    const int wc   = w & 3;
    const int bm   = blockIdx.y * GBM;
    const int bn   = blockIdx.x * GBN;

    float c[4][4][4];
#pragma unroll
    for (int mt = 0; mt < 4; mt++)
#pragma unroll
        for (int nt = 0; nt < 4; nt++)
#pragma unroll
            for (int j = 0; j < 4; j++) c[mt][nt][j] = 0.f;

    const int lq = lane >> 3;
    const int lr = lane & 7;
    const int a_row_off = wr * 64 + lr + 8 * (lq & 1);
    const int a_col_off = 4 * (lq >> 1);

    const int NKT = CC / GBK;   // 32

    // ---- load tile kt into stage st ----
    auto load_tile = [&](int kt, int st) {
        float* As = gsm + st * G_STAGE;
        float* Bs = As + G_ASZ;
#pragma unroll
        for (int i = 0; i < 4; i++) {
            int f = tid + i * 256;
            int row = f >> 3, c4 = f & 7;
            cp16(&As[row * AS_STRIDE + c4 * 4],
                 A + (size_t)(bm + row) * CC + kt * GBK + c4 * 4);
        }
#pragma unroll
        for (int i = 0; i < 4; i++) {
            int f = tid + i * 256;
            int k = f >> 5, c4 = f & 31;
            cp16(&Bs[k * BS_STRIDE + c4 * 4],
                 W + (size_t)(kt * GBK + k) * CC + bn + c4 * 4);
        }
        CP_COMMIT();
    };

    load_tile(0, 0);

    for (int kt = 0; kt < NKT; kt++) {
        if (kt + 1 < NKT) {
            load_tile(kt + 1, (kt + 1) & 1);
            CP_WAIT(1);
        } else {
            CP_WAIT(0);
        }
        __syncthreads();

        float* As = gsm + (kt & 1) * G_STAGE;
        float* Bs = As + G_ASZ;

#pragma unroll
        for (int ks = 0; ks < 4; ks++) {
            unsigned a[4][4];
#pragma unroll
            for (int mt = 0; mt < 4; mt++) {
                unsigned addr = (unsigned)__cvta_generic_to_shared(
                    &As[(a_row_off + mt * 16) * AS_STRIDE + ks * 8 + a_col_off]);
                asm volatile(
                    "ldmatrix.sync.aligned.m8n8.x4.shared.b16 {%0,%1,%2,%3}, [%4];\n"
                    : "=r"(a[mt][0]), "=r"(a[mt][1]), "=r"(a[mt][2]), "=r"(a[mt][3])
                    : "r"(addr));
#pragma unroll
                for (int j = 0; j < 4; j++) CVT_TF32(a[mt][j]);
            }
#pragma unroll
            for (int nt = 0; nt < 4; nt++) {
                int n = wc * 32 + nt * 8 + (lane >> 2);
                int k = ks * 8 + (lane & 3);
                unsigned b0 = __float_as_uint(Bs[k * BS_STRIDE + n]);
                unsigned b1 = __float_as_uint(Bs[(k + 4) * BS_STRIDE + n]);
                CVT_TF32(b0);
                CVT_TF32(b1);
#pragma unroll
                for (int mt = 0; mt < 4; mt++)
                    mma_tf32(c[mt][nt], a[mt], b0, b1);
            }
        }
        __syncthreads();   // stage consumed; next-next load may overwrite
    }

#pragma unroll
    for (int mt = 0; mt < 4; mt++) {
        int row = bm + wr * 64 + mt * 16 + (lane >> 2);
#pragma unroll
        for (int nt = 0; nt < 4; nt++) {
            int col = bn + wc * 32 + nt * 8 + 2 * (lane & 3);
            float b0 = bias[col], b1 = bias[col + 1];
            float2 v0 = make_float2(c[mt][nt][0] + b0, c[mt][nt][1] + b1);
            float2 v1 = make_float2(c[mt][nt][2] + b0, c[mt][nt][3] + b1);
            *(float2*)&C[(size_t)row * CC + col] = v0;
            *(float2*)&C[(size_t)(row + 8) * CC + col] = v1;
        }
    }
}

// ---------------------------------------------------------------------------
// RoPE + transpose [B,T,H,D] -> [B,H,T,D]. (verified)
// ---------------------------------------------------------------------------
__global__ void rope_transpose_kernel()
{
    int idx = blockIdx.x * blockDim.x + threadIdx.x;
    if (idx >= BQ * HH * TT * 16) return;
    int j = idx & 15;
    int t = (idx >> 4) & (TT - 1);
    int h = (idx >> 15) & (HH - 1);
    int b = idx >> 19;

    const size_t src = ((size_t)(b * TT + t)) * CC + h * DD;
    const size_t dst = ((size_t)((b * HH + h) * TT + t)) * DD;

    float inv = exp2f(-(float)j * 0.8304820237218405f);
    float ang = (float)t * inv;
    float sn, cs;
    sincosf(ang, &sn, &cs);

    float q0 = g_q[src + j], q1 = g_q[src + j + 16];
    g_Q[dst + j]      = q0 * cs - q1 * sn;
    g_Q[dst + j + 16] = q1 * cs + q0 * sn;

    float k0 = g_k[src + j], k1 = g_k[src + j + 16];
    g_K[dst + j]      = k0 * cs - k1 * sn;
    g_K[dst + j + 16] = k1 * cs + k0 * sn;

    g_Q[dst + j + 32] = g_q[src + j + 32];
    g_Q[dst + j + 48] = g_q[src + j + 48];
    g_K[dst + j + 32] = g_k[src + j + 32];
    g_K[dst + j + 48] = g_k[src + j + 48];

    g_V[dst + j]      = g_v[src + j];
    g_V[dst + j + 16] = g_v[src + j + 16];
    g_V[dst + j + 32] = g_v[src + j + 32];
    g_V[dst + j + 48] = g_v[src + j + 48];
}

// ---------------------------------------------------------------------------
// Flash attention, tf32 mma, 2-stage K/V pipeline. 64 Q rows/CTA, 128 thr.
// smem: Qs[64][68] | {Ks[64][68] Vs[64][72]} x2 | Ps[64][68]
// ---------------------------------------------------------------------------
#define QS_STR 68
#define KS_STR 68
#define VS_STR 72
#define PS_STR 68
#define A_QSZ (64 * QS_STR)
#define A_KSZ (64 * KS_STR)
#define A_VSZ (64 * VS_STR)
#define A_PSZ (64 * PS_STR)
#define A_KVSTAGE (A_KSZ + A_VSZ)
#define ATT_SMEM_BYTES ((A_QSZ + 2 * A_KVSTAGE + A_PSZ) * 4)

__global__ __launch_bounds__(128) void attn_tc_kernel()
{
    extern __shared__ __align__(16) float sm[];
    float* Qs  = sm;                          // 64 x 68
    float* KV0 = Qs + A_QSZ;                  // stage 0: Ks | Vs
    float* KV1 = KV0 + A_KVSTAGE;             // stage 1
    float* Ps  = KV1 + A_KVSTAGE;             // 64 x 68

    const int bh = blockIdx.y;                // b*16 + h
    const int qb = blockIdx.x;
    const int tid  = threadIdx.x;
    const int lane = tid & 31;
    const int w    = tid >> 5;

    const float* Qg = g_Q + (size_t)bh * TT * DD + (size_t)qb * 64 * DD;
    const float* Kg = g_K + (size_t)bh * TT * DD;
    const float* Vg = g_V + (size_t)bh * TT * DD;

    // ---- load Q tile (once) ----
#pragma unroll
    for (int i = 0; i < 8; i++) {
        int idx = tid + i * 128;
        int r = idx >> 4, c4 = (idx & 15) << 2;
        *(float4*)&Qs[r * QS_STR + c4] = *(const float4*)&Qg[r * DD + c4];
    }

    // ---- prefetch jt=0 K/V into stage 0 ----
    auto load_kv = [&](int jt, float* stage) {
        float* Ks = stage;
        float* Vs = stage + A_KSZ;
        const float* Kt = Kg + (size_t)jt * 64 * DD;
        const float* Vt = Vg + (size_t)jt * 64 * DD;
#pragma unroll
        for (int i = 0; i < 8; i++) {
            int idx = tid + i * 128;
            int r = idx >> 4, c4 = (idx & 15) << 2;
            cp16(&Ks[r * KS_STR + c4], Kt + r * DD + c4);
            cp16(&Vs[r * VS_STR + c4], Vt + r * DD + c4);
        }
        CP_COMMIT();
    };
    load_kv(0, KV0);

    __syncthreads();   // Qs visible

    // ---- preload Q fragments ----
    const int lq = lane >> 3;
    const int lr = lane & 7;
    const int a_row = w * 16 + lr + 8 * (lq & 1);
    const int a_col = 4 * (lq >> 1);
    unsigned qf[8][4];
#pragma unroll
    for (int ks = 0; ks < 8; ks++) {
        unsigned addr = (unsigned)__cvta_generic_to_shared(
            &Qs[a_row * QS_STR + ks * 8 + a_col]);
        asm volatile(
            "ldmatrix.sync.aligned.m8n8.x4.shared.b16 {%0,%1,%2,%3}, [%4];\n"
            : "=r"(qf[ks][0]), "=r"(qf[ks][1]), "=r"(qf[ks][2]), "=r"(qf[ks][3])
            : "r"(addr));
#pragma unroll
        for (int j = 0; j < 4; j++) CVT_TF32(qf[ks][j]);
    }

    const int b_row = 8 * (lq >> 1) + lr;
    const int b_col = 4 * (lq & 1);

    const int fr = lane >> 2;
    const int fc = lane & 3;
    const int row0_l = w * 16 + fr;
    const int row1_l = row0_l + 8;

    float m0 = -3.0e38f, m1 = -3.0e38f, l0 = 0.f, l1 = 0.f;
    float o[8][4];
#pragma unroll
    for (int nt = 0; nt < 8; nt++)
#pragma unroll
        for (int j = 0; j < 4; j++) o[nt][j] = 0.f;

    for (int jt = 0; jt <= qb; jt++) {
        if (jt < qb) {
            load_kv(jt + 1, (jt & 1) ? KV0 : KV1);
            CP_WAIT(1);
        } else {
            CP_WAIT(0);
        }
        __syncthreads();

        float* Ks = (jt & 1) ? KV1 : KV0;
        float* Vs = Ks + A_KSZ;

        // ---- S = Q @ K^T ----
        float c[8][4];
#pragma unroll
        for (int nt = 0; nt < 8; nt++)
#pragma unroll
            for (int j = 0; j < 4; j++) c[nt][j] = 0.f;

#pragma unroll
        for (int ks = 0; ks < 8; ks++) {
#pragma unroll
            for (int ntp = 0; ntp < 4; ntp++) {
                unsigned b[4];
                unsigned addr = (unsigned)__cvta_generic_to_shared(
                    &Ks[(ntp * 16 + b_row) * KS_STR + ks * 8 + b_col]);
                asm volatile(
                    "ldmatrix.sync.aligned.m8n8.x4.shared.b16 {%0,%1,%2,%3}, [%4];\n"
                    : "=r"(b[0]), "=r"(b[1]), "=r"(b[2]), "=r"(b[3])
                    : "r"(addr));
#pragma unroll
                for (int j = 0; j < 4; j++) CVT_TF32(b[j]);
                mma_tf32(c[2 * ntp],     qf[ks], b[0], b[1]);
                mma_tf32(c[2 * ntp + 1], qf[ks], b[2], b[3]);
            }
        }

        // ---- scale + causal mask ----
        if (jt == qb) {
#pragma unroll
            for (int nt = 0; nt < 8; nt++) {
                int col0 = nt * 8 + 2 * fc, col1 = col0 + 1;
                c[nt][0] = (col0 <= row0_l) ? c[nt][0] * 0.125f : -1.0e30f;
                c[nt][1] = (col1 <= row0_l) ? c[nt][1] * 0.125f : -1.0e30f;
                c[nt][2] = (col0 <= row1_l) ? c[nt][2] * 0.125f : -1.0e30f;
                c[nt][3] = (col1 <= row1_l) ? c[nt][3] * 0.125f : -1.0e30f;
            }
        } else {
#pragma unroll
            for (int nt = 0; nt < 8; nt++)
#pragma unroll
                for (int j = 0; j < 4; j++) c[nt][j] *= 0.125f;
        }

        // ---- online softmax ----
        float mx0 = -3.0e38f, mx1 = -3.0e38f;
#pragma unroll
        for (int nt = 0; nt < 8; nt++) {
            mx0 = fmaxf(mx0, fmaxf(c[nt][0], c[nt][1]));
            mx1 = fmaxf(mx1, fmaxf(c[nt][2], c[nt][3]));
        }
        mx0 = fmaxf(mx0, __shfl_xor_sync(0xffffffffu, mx0, 1));
        mx0 = fmaxf(mx0, __shfl_xor_sync(0xffffffffu, mx0, 2));
        mx1 = fmaxf(mx1, __shfl_xor_sync(0xffffffffu, mx1, 1));
        mx1 = fmaxf(mx1, __shfl_xor_sync(0xffffffffu, mx1, 2));
        float mn0 = fmaxf(m0, mx0), mn1 = fmaxf(m1, mx1);
        float al0 = __expf(m0 - mn0), al1 = __expf(m1 - mn1);

        float rs0 = 0.f, rs1 = 0.f;
#pragma unroll
        for (int nt = 0; nt < 8; nt++) {
            c[nt][0] = __expf(c[nt][0] - mn0);
            c[nt][1] = __expf(c[nt][1] - mn0);
            c[nt][2] = __expf(c[nt][2] - mn1);
            c[nt][3] = __expf(c[nt][3] - mn1);
            rs0 += c[nt][0] + c[nt][1];
            rs1 += c[nt][2] + c[nt][3];
        }
        rs0 += __shfl_xor_sync(0xffffffffu, rs0, 1);
        rs0 += __shfl_xor_sync(0xffffffffu, rs0, 2);
        rs1 += __shfl_xor_sync(0xffffffffu, rs1, 1);
        rs1 += __shfl_xor_sync(0xffffffffu, rs1, 2);
        l0 = l0 * al0 + rs0; m0 = mn0;
        l1 = l1 * al1 + rs1; m1 = mn1;

#pragma unroll
        for (int nt = 0; nt < 8; nt++) {
            o[nt][0] *= al0; o[nt][1] *= al0;
            o[nt][2] *= al1; o[nt][3] *= al1;
            *(float2*)&Ps[row0_l * PS_STR + nt * 8 + 2 * fc] =
                make_float2(c[nt][0], c[nt][1]);
            *(float2*)&Ps[row1_l * PS_STR + nt * 8 + 2 * fc] =
                make_float2(c[nt][2], c[nt][3]);
        }
        __syncwarp();

        // ---- O += P @ V ----
#pragma unroll
        for (int ks = 0; ks < 8; ks++) {
            unsigned pf[4];
            unsigned addr = (unsigned)__cvta_generic_to_shared(
                &Ps[a_row * PS_STR + ks * 8 + a_col]);
            asm volatile(
                "ldmatrix.sync.aligned.m8n8.x4.shared.b16 {%0,%1,%2,%3}, [%4];\n"
                : "=r"(pf[0]), "=r"(pf[1]), "=r"(pf[2]), "=r"(pf[3])
                : "r"(addr));
#pragma unroll
            for (int j = 0; j < 4; j++) CVT_TF32(pf[j]);
            int k = ks * 8 + fc;
#pragma unroll
            for (int nt = 0; nt < 8; nt++) {
                int n = nt * 8 + fr;
                unsigned b0 = __float_as_uint(Vs[k * VS_STR + n]);
                unsigned b1 = __float_as_uint(Vs[(k + 4) * VS_STR + n]);
                CVT_TF32(b0);
                CVT_TF32(b1);
                mma_tf32(o[nt], pf, b0, b1);
            }
        }
        __syncthreads();   // stage + Ps consumed; prefetch may overwrite next iter
    }

    // ---- epilogue: normalize, write to g_att [B,T,C] ----
    const int b = bh >> 4, h = bh & 15;
    float inv0 = 1.f / l0, inv1 = 1.f / l1;
    size_t base0 = ((size_t)(b * TT + qb * 64 + row0_l)) * CC + h * DD;
    size_t base1 = ((size_t)(b * TT + qb * 64 + row1_l)) * CC + h * DD;
#pragma unroll
    for (int nt = 0; nt < 8; nt++) {
        int col = nt * 8 + 2 * fc;
        *(float2*)&g_att[base0 + col] =
            make_float2(o[nt][0] * inv0, o[nt][1] * inv0);
        *(float2*)&g_att[base1 + col] =
            make_float2(o[nt][2] * inv1, o[nt][3] * inv1);
    }
}

// ---------------------------------------------------------------------------
extern "C" void kernel_launch(void* const* d_in, const int* in_sizes, int n_in,
                              void* d_out, int out_size)
{
    const float* x  = (const float*)d_in[0];
    const float* Wq = (const float*)d_in[1];
    const float* bq = (const float*)d_in[2];
    const float* Wk = (const float*)d_in[3];
    const float* bk = (const float*)d_in[4];
    const float* Wv = (const float*)d_in[5];
    const float* bv = (const float*)d_in[6];
    const float* Wo = (const float*)d_in[7];
    const float* bo = (const float*)d_in[8];
    float* out = (float*)d_out;

    // Idempotent, host-side, capture-safe: call every time (no static guards).
    cudaFuncSetAttribute(gemm_tf32,
                         cudaFuncAttributeMaxDynamicSharedMemorySize,
                         G_SMEM_BYTES);
    cudaFuncSetAttribute(attn_tc_kernel,
                         cudaFuncAttributeMaxDynamicSharedMemorySize,
                         ATT_SMEM_BYTES);

    dim3 gg(CC / GBN, MM / GBM); // (8, 32)

    gemm_tf32<<<gg, 256, G_SMEM_BYTES>>>(x, Wq, bq, nullptr, 0, 0);
    gemm_tf32<<<gg, 256, G_SMEM_BYTES>>>(x, Wk, bk, nullptr, 0, 1);
    gemm_tf32<<<gg, 256, G_SMEM_BYTES>>>(x, Wv, bv, nullptr, 0, 2);

    rope_transpose_kernel<<<(BQ * HH * TT * 16) / 256, 256>>>();

    attn_tc_kernel<<<dim3(TT / 64, BQ * HH), 128, ATT_SMEM_BYTES>>>();

    gemm_tf32<<<gg, 256, G_SMEM_BYTES>>>(nullptr, Wo, bo, out, 1, 3);
}

// round 9
// speedup vs baseline: 1.0921x; 1.0921x over previous
#include <cuda_runtime.h>
#include <cuda_bf16.h>
#include <math.h>

// Problem constants (fixed by the reference)
#define BQ 2
#define TT 2048
#define CC 1024
#define HH 16
#define DD 64
#define MM (BQ*TT)   // 4096 rows

#define REG_FLOATS (CC*CC)   // 1M floats per weight; x is 4M floats

// Scratch (device globals: allocation-free rule)
__device__ float g_q[(size_t)MM*CC];
__device__ float g_k[(size_t)MM*CC];
__device__ float g_v[(size_t)MM*CC];
__device__ float g_Q[(size_t)MM*CC];   // [B,H,T,D], rope applied + tf32-rounded
__device__ float g_K[(size_t)MM*CC];   // [B,H,T,D], rope applied + tf32-rounded
__device__ float g_V[(size_t)MM*CC];   // [B,H,T,D], tf32-rounded
__device__ float g_att[(size_t)MM*CC]; // [B,T,C] attention out, tf32-rounded
// Pre-rounded inputs: [ x (4M) | Wq (1M) | Wk | Wv | Wo ]
__device__ float g_pre[(size_t)MM*CC + 4*(size_t)REG_FLOATS];

__device__ __forceinline__ void cp16(void* dst, const void* src) {
    unsigned d = (unsigned)__cvta_generic_to_shared(dst);
    asm volatile("cp.async.cg.shared.global [%0], [%1], 16;\n" :: "r"(d), "l"(src));
}
#define CP_COMMIT() asm volatile("cp.async.commit_group;\n")
#define CP_WAIT(n)  asm volatile("cp.async.wait_group %0;\n" :: "n"(n))

__device__ __forceinline__ void mma_tf32(float c[4], const unsigned a[4],
                                         unsigned b0, unsigned b1) {
    asm volatile(
        "mma.sync.aligned.m16n8k8.row.col.f32.tf32.tf32.f32 "
        "{%0,%1,%2,%3}, {%4,%5,%6,%7}, {%8,%9}, {%0,%1,%2,%3};\n"
        : "+f"(c[0]), "+f"(c[1]), "+f"(c[2]), "+f"(c[3])
        : "r"(a[0]), "r"(a[1]), "r"(a[2]), "r"(a[3]), "r"(b0), "r"(b1));
}
#define CVT_TF32(x) asm volatile("cvt.rna.tf32.f32 %0, %0;\n" : "+r"(x))

__device__ __forceinline__ float round_tf32(float f) {
    unsigned u = __float_as_uint(f);
    CVT_TF32(u);
    return __uint_as_float(u);
}

// ---------------------------------------------------------------------------
// Pre-round x + 4 weight matrices to tf32 (rna) once. 1 float4/thread.
// Regions: 0..3 = x (4M floats), 4..7 = Wq,Wk,Wv,Wo (1M each).
// ---------------------------------------------------------------------------
__global__ void preround_kernel(const float* __restrict__ x,
                                const float* __restrict__ Wq,
                                const float* __restrict__ Wk,
                                const float* __restrict__ Wv,
                                const float* __restrict__ Wo)
{
    size_t t = (size_t)blockIdx.x * blockDim.x + threadIdx.x;   // float4 index
    const size_t RQ = REG_FLOATS / 4;   // 256K float4 per 1M-float region
    size_t r4 = t / RQ;                 // 0..7
    size_t off = (t % RQ) * 4;
    const float* src;
    float* dst;
    if (r4 < 4) {                       // x region (4 x 1M floats)
        src = x + r4 * REG_FLOATS;
        dst = g_pre + r4 * REG_FLOATS;
    } else {
        const float* ws[4] = {Wq, Wk, Wv, Wo};
        src = ws[r4 - 4];
        dst = g_pre + (size_t)MM * CC + (r4 - 4) * (size_t)REG_FLOATS;
    }
    float4 v = *(const float4*)(src + off);
    v.x = round_tf32(v.x); v.y = round_tf32(v.y);
    v.z = round_tf32(v.z); v.w = round_tf32(v.w);
    *(float4*)(dst + off) = v;
}

// ---------------------------------------------------------------------------
// TF32 tensor-core GEMM, 2-stage pipelined, CVT-free mainloop.
// A: srcFlag 0 -> g_pre[x], 1 -> g_att (both pre-rounded).
// W: g_pre weight region dstFlag. C: dstFlag 0/1/2 -> g_q/g_k/g_v, 3 -> Cext.
// ---------------------------------------------------------------------------
#define GBM 128
#define GBN 128
#define GBK 32
#define AS_STRIDE 36
#define BS_STRIDE 136
#define G_ASZ (GBM * AS_STRIDE)            // 4608 floats
#define G_BSZ (GBK * BS_STRIDE)            // 4352 floats
#define G_STAGE (G_ASZ + G_BSZ)            // 8960 floats
#define G_SMEM_BYTES (2 * G_STAGE * 4)     // 71680 B

__global__ __launch_bounds__(256, 2) void gemm_tf32(
    const float* __restrict__ bias, float* __restrict__ Cext,
    int srcFlag, int dstFlag)
{
    const float* A = srcFlag ? g_att : g_pre;
    const float* W = g_pre + (size_t)MM * CC + (size_t)dstFlag * REG_FLOATS;
    float* C = (dstFlag == 0) ? g_q : (dstFlag == 1) ? g_k
             : (dstFlag == 2) ? g_v : Cext;

    extern __shared__ __align__(16) float gsm[];

    const int tid  = threadIdx.x;
    const int lane = tid & 31;
    const int w    = tid >> 5;
    const int wr   = w >> 2;
    const int wc   = w & 3;
    const int bm   = blockIdx.y * GBM;
    const int bn   = blockIdx.x * GBN;

    float c[4][4][4];
#pragma unroll
    for (int mt = 0; mt < 4; mt++)
#pragma unroll
        for (int nt = 0; nt < 4; nt++)
#pragma unroll
            for (int j = 0; j < 4; j++) c[mt][nt][j] = 0.f;

    const int lq = lane >> 3;
    const int lr = lane & 7;
    const int a_row_off = wr * 64 + lr + 8 * (lq & 1);
    const int a_col_off = 4 * (lq >> 1);

    const int NKT = CC / GBK;   // 32

    auto load_tile = [&](int kt, int st) {
        float* As = gsm + st * G_STAGE;
        float* Bs = As + G_ASZ;
#pragma unroll
        for (int i = 0; i < 4; i++) {
            int f = tid + i * 256;
            int row = f >> 3, c4 = f & 7;
            cp16(&As[row * AS_STRIDE + c4 * 4],
                 A + (size_t)(bm + row) * CC + kt * GBK + c4 * 4);
        }
#pragma unroll
        for (int i = 0; i < 4; i++) {
            int f = tid + i * 256;
            int k = f >> 5, c4 = f & 31;
            cp16(&Bs[k * BS_STRIDE + c4 * 4],
                 W + (size_t)(kt * GBK + k) * CC + bn + c4 * 4);
        }
        CP_COMMIT();
    };

    load_tile(0, 0);

    for (int kt = 0; kt < NKT; kt++) {
        if (kt + 1 < NKT) {
            load_tile(kt + 1, (kt + 1) & 1);
            CP_WAIT(1);
        } else {
            CP_WAIT(0);
        }
        __syncthreads();

        float* As = gsm + (kt & 1) * G_STAGE;
        float* Bs = As + G_ASZ;

#pragma unroll
        for (int ks = 0; ks < 4; ks++) {
            unsigned a[4][4];
#pragma unroll
            for (int mt = 0; mt < 4; mt++) {
                unsigned addr = (unsigned)__cvta_generic_to_shared(
                    &As[(a_row_off + mt * 16) * AS_STRIDE + ks * 8 + a_col_off]);
                asm volatile(
                    "ldmatrix.sync.aligned.m8n8.x4.shared.b16 {%0,%1,%2,%3}, [%4];\n"
                    : "=r"(a[mt][0]), "=r"(a[mt][1]), "=r"(a[mt][2]), "=r"(a[mt][3])
                    : "r"(addr));
            }
#pragma unroll
            for (int nt = 0; nt < 4; nt++) {
                int n = wc * 32 + nt * 8 + (lane >> 2);
                int k = ks * 8 + (lane & 3);
                unsigned b0 = __float_as_uint(Bs[k * BS_STRIDE + n]);
                unsigned b1 = __float_as_uint(Bs[(k + 4) * BS_STRIDE + n]);
#pragma unroll
                for (int mt = 0; mt < 4; mt++)
                    mma_tf32(c[mt][nt], a[mt], b0, b1);
            }
        }
        __syncthreads();
    }

#pragma unroll
    for (int mt = 0; mt < 4; mt++) {
        int row = bm + wr * 64 + mt * 16 + (lane >> 2);
#pragma unroll
        for (int nt = 0; nt < 4; nt++) {
            int col = bn + wc * 32 + nt * 8 + 2 * (lane & 3);
            float b0 = bias[col], b1 = bias[col + 1];
            float2 v0 = make_float2(c[mt][nt][0] + b0, c[mt][nt][1] + b1);
            float2 v1 = make_float2(c[mt][nt][2] + b0, c[mt][nt][3] + b1);
            *(float2*)&C[(size_t)row * CC + col] = v0;
            *(float2*)&C[(size_t)(row + 8) * CC + col] = v1;
        }
    }
}

// ---------------------------------------------------------------------------
// RoPE + transpose [B,T,H,D] -> [B,H,T,D], outputs tf32-rounded.
// ---------------------------------------------------------------------------
__global__ void rope_transpose_kernel()
{
    int idx = blockIdx.x * blockDim.x + threadIdx.x;
    if (idx >= BQ * HH * TT * 16) return;
    int j = idx & 15;
    int t = (idx >> 4) & (TT - 1);
    int h = (idx >> 15) & (HH - 1);
    int b = idx >> 19;

    const size_t src = ((size_t)(b * TT + t)) * CC + h * DD;
    const size_t dst = ((size_t)((b * HH + h) * TT + t)) * DD;

    float inv = exp2f(-(float)j * 0.8304820237218405f);
    float ang = (float)t * inv;
    float sn, cs;
    sincosf(ang, &sn, &cs);

    float q0 = g_q[src + j], q1 = g_q[src + j + 16];
    g_Q[dst + j]      = round_tf32(q0 * cs - q1 * sn);
    g_Q[dst + j + 16] = round_tf32(q1 * cs + q0 * sn);

    float k0 = g_k[src + j], k1 = g_k[src + j + 16];
    g_K[dst + j]      = round_tf32(k0 * cs - k1 * sn);
    g_K[dst + j + 16] = round_tf32(k1 * cs + k0 * sn);

    g_Q[dst + j + 32] = round_tf32(g_q[src + j + 32]);
    g_Q[dst + j + 48] = round_tf32(g_q[src + j + 48]);
    g_K[dst + j + 32] = round_tf32(g_k[src + j + 32]);
    g_K[dst + j + 48] = round_tf32(g_k[src + j + 48]);

    g_V[dst + j]      = round_tf32(g_v[src + j]);
    g_V[dst + j + 16] = round_tf32(g_v[src + j + 16]);
    g_V[dst + j + 32] = round_tf32(g_v[src + j + 32]);
    g_V[dst + j + 48] = round_tf32(g_v[src + j + 48]);
}

// ---------------------------------------------------------------------------
// Flash attention, tf32 mma, 2-stage K/V pipeline, CVT-free operand loads
// (Q/K/V pre-rounded; only P-after-exp needs conversion).
// ---------------------------------------------------------------------------
#define QS_STR 68
#define KS_STR 68
#define VS_STR 72
#define PS_STR 68
#define A_QSZ (64 * QS_STR)
#define A_KSZ (64 * KS_STR)
#define A_VSZ (64 * VS_STR)
#define A_PSZ (64 * PS_STR)
#define A_KVSTAGE (A_KSZ + A_VSZ)
#define ATT_SMEM_BYTES ((A_QSZ + 2 * A_KVSTAGE + A_PSZ) * 4)

__global__ __launch_bounds__(128) void attn_tc_kernel()
{
    extern __shared__ __align__(16) float sm[];
    float* Qs  = sm;
    float* KV0 = Qs + A_QSZ;
    float* KV1 = KV0 + A_KVSTAGE;
    float* Ps  = KV1 + A_KVSTAGE;

    const int bh = blockIdx.y;
    const int qb = blockIdx.x;
    const int tid  = threadIdx.x;
    const int lane = tid & 31;
    const int w    = tid >> 5;

    const float* Qg = g_Q + (size_t)bh * TT * DD + (size_t)qb * 64 * DD;
    const float* Kg = g_K + (size_t)bh * TT * DD;
    const float* Vg = g_V + (size_t)bh * TT * DD;

#pragma unroll
    for (int i = 0; i < 8; i++) {
        int idx = tid + i * 128;
        int r = idx >> 4, c4 = (idx & 15) << 2;
        *(float4*)&Qs[r * QS_STR + c4] = *(const float4*)&Qg[r * DD + c4];
    }

    auto load_kv = [&](int jt, float* stage) {
        float* Ks = stage;
        float* Vs = stage + A_KSZ;
        const float* Kt = Kg + (size_t)jt * 64 * DD;
        const float* Vt = Vg + (size_t)jt * 64 * DD;
#pragma unroll
        for (int i = 0; i < 8; i++) {
            int idx = tid + i * 128;
            int r = idx >> 4, c4 = (idx & 15) << 2;
            cp16(&Ks[r * KS_STR + c4], Kt + r * DD + c4);
            cp16(&Vs[r * VS_STR + c4], Vt + r * DD + c4);
        }
        CP_COMMIT();
    };
    load_kv(0, KV0);

    __syncthreads();

    const int lq = lane >> 3;
    const int lr = lane & 7;
    const int a_row = w * 16 + lr + 8 * (lq & 1);
    const int a_col = 4 * (lq >> 1);
    unsigned qf[8][4];
#pragma unroll
    for (int ks = 0; ks < 8; ks++) {
        unsigned addr = (unsigned)__cvta_generic_to_shared(
            &Qs[a_row * QS_STR + ks * 8 + a_col]);
        asm volatile(
            "ldmatrix.sync.aligned.m8n8.x4.shared.b16 {%0,%1,%2,%3}, [%4];\n"
            : "=r"(qf[ks][0]), "=r"(qf[ks][1]), "=r"(qf[ks][2]), "=r"(qf[ks][3])
            : "r"(addr));
    }

    const int b_row = 8 * (lq >> 1) + lr;
    const int b_col = 4 * (lq & 1);

    const int fr = lane >> 2;
    const int fc = lane & 3;
    const int row0_l = w * 16 + fr;
    const int row1_l = row0_l + 8;

    float m0 = -3.0e38f, m1 = -3.0e38f, l0 = 0.f, l1 = 0.f;
    float o[8][4];
#pragma unroll
    for (int nt = 0; nt < 8; nt++)
#pragma unroll
        for (int j = 0; j < 4; j++) o[nt][j] = 0.f;

    for (int jt = 0; jt <= qb; jt++) {
        if (jt < qb) {
            load_kv(jt + 1, (jt & 1) ? KV0 : KV1);
            CP_WAIT(1);
        } else {
            CP_WAIT(0);
        }
        __syncthreads();

        float* Ks = (jt & 1) ? KV1 : KV0;
        float* Vs = Ks + A_KSZ;

        float c[8][4];
#pragma unroll
        for (int nt = 0; nt < 8; nt++)
#pragma unroll
            for (int j = 0; j < 4; j++) c[nt][j] = 0.f;

#pragma unroll
        for (int ks = 0; ks < 8; ks++) {
#pragma unroll
            for (int ntp = 0; ntp < 4; ntp++) {
                unsigned b[4];
                unsigned addr = (unsigned)__cvta_generic_to_shared(
                    &Ks[(ntp * 16 + b_row) * KS_STR + ks * 8 + b_col]);
                asm volatile(
                    "ldmatrix.sync.aligned.m8n8.x4.shared.b16 {%0,%1,%2,%3}, [%4];\n"
                    : "=r"(b[0]), "=r"(b[1]), "=r"(b[2]), "=r"(b[3])
                    : "r"(addr));
                mma_tf32(c[2 * ntp],     qf[ks], b[0], b[1]);
                mma_tf32(c[2 * ntp + 1], qf[ks], b[2], b[3]);
            }
        }

        if (jt == qb) {
#pragma unroll
            for (int nt = 0; nt < 8; nt++) {
                int col0 = nt * 8 + 2 * fc, col1 = col0 + 1;
                c[nt][0] = (col0 <= row0_l) ? c[nt][0] * 0.125f : -1.0e30f;
                c[nt][1] = (col1 <= row0_l) ? c[nt][1] * 0.125f : -1.0e30f;
                c[nt][2] = (col0 <= row1_l) ? c[nt][2] * 0.125f : -1.0e30f;
                c[nt][3] = (col1 <= row1_l) ? c[nt][3] * 0.125f : -1.0e30f;
            }
        } else {
#pragma unroll
            for (int nt = 0; nt < 8; nt++)
#pragma unroll
                for (int j = 0; j < 4; j++) c[nt][j] *= 0.125f;
        }

        float mx0 = -3.0e38f, mx1 = -3.0e38f;
#pragma unroll
        for (int nt = 0; nt < 8; nt++) {
            mx0 = fmaxf(mx0, fmaxf(c[nt][0], c[nt][1]));
            mx1 = fmaxf(mx1, fmaxf(c[nt][2], c[nt][3]));
        }
        mx0 = fmaxf(mx0, __shfl_xor_sync(0xffffffffu, mx0, 1));
        mx0 = fmaxf(mx0, __shfl_xor_sync(0xffffffffu, mx0, 2));
        mx1 = fmaxf(mx1, __shfl_xor_sync(0xffffffffu, mx1, 1));
        mx1 = fmaxf(mx1, __shfl_xor_sync(0xffffffffu, mx1, 2));
        float mn0 = fmaxf(m0, mx0), mn1 = fmaxf(m1, mx1);
        float al0 = __expf(m0 - mn0), al1 = __expf(m1 - mn1);

        float rs0 = 0.f, rs1 = 0.f;
#pragma unroll
        for (int nt = 0; nt < 8; nt++) {
            c[nt][0] = __expf(c[nt][0] - mn0);
            c[nt][1] = __expf(c[nt][1] - mn0);
            c[nt][2] = __expf(c[nt][2] - mn1);
            c[nt][3] = __expf(c[nt][3] - mn1);
            rs0 += c[nt][0] + c[nt][1];
            rs1 += c[nt][2] + c[nt][3];
        }
        rs0 += __shfl_xor_sync(0xffffffffu, rs0, 1);
        rs0 += __shfl_xor_sync(0xffffffffu, rs0, 2);
        rs1 += __shfl_xor_sync(0xffffffffu, rs1, 1);
        rs1 += __shfl_xor_sync(0xffffffffu, rs1, 2);
        l0 = l0 * al0 + rs0; m0 = mn0;
        l1 = l1 * al1 + rs1; m1 = mn1;

#pragma unroll
        for (int nt = 0; nt < 8; nt++) {
            o[nt][0] *= al0; o[nt][1] *= al0;
            o[nt][2] *= al1; o[nt][3] *= al1;
            *(float2*)&Ps[row0_l * PS_STR + nt * 8 + 2 * fc] =
                make_float2(c[nt][0], c[nt][1]);
            *(float2*)&Ps[row1_l * PS_STR + nt * 8 + 2 * fc] =
                make_float2(c[nt][2], c[nt][3]);
        }
        __syncwarp();

#pragma unroll
        for (int ks = 0; ks < 8; ks++) {
            unsigned pf[4];
            unsigned addr = (unsigned)__cvta_generic_to_shared(
                &Ps[a_row * PS_STR + ks * 8 + a_col]);
            asm volatile(
                "ldmatrix.sync.aligned.m8n8.x4.shared.b16 {%0,%1,%2,%3}, [%4];\n"
                : "=r"(pf[0]), "=r"(pf[1]), "=r"(pf[2]), "=r"(pf[3])
                : "r"(addr));
#pragma unroll
            for (int j = 0; j < 4; j++) CVT_TF32(pf[j]);
            int k = ks * 8 + fc;
#pragma unroll
            for (int nt = 0; nt < 8; nt++) {
                int n = nt * 8 + fr;
                unsigned b0 = __float_as_uint(Vs[k * VS_STR + n]);
                unsigned b1 = __float_as_uint(Vs[(k + 4) * VS_STR + n]);
                mma_tf32(o[nt], pf, b0, b1);
            }
        }
        __syncthreads();
    }

    // epilogue: normalize, tf32-round (feeds Wo GEMM), write g_att [B,T,C]
    const int b = bh >> 4, h = bh & 15;
    float inv0 = 1.f / l0, inv1 = 1.f / l1;
    size_t base0 = ((size_t)(b * TT + qb * 64 + row0_l)) * CC + h * DD;
    size_t base1 = ((size_t)(b * TT + qb * 64 + row1_l)) * CC + h * DD;
#pragma unroll
    for (int nt = 0; nt < 8; nt++) {
        int col = nt * 8 + 2 * fc;
        *(float2*)&g_att[base0 + col] =
            make_float2(round_tf32(o[nt][0] * inv0), round_tf32(o[nt][1] * inv0));
        *(float2*)&g_att[base1 + col] =
            make_float2(round_tf32(o[nt][2] * inv1), round_tf32(o[nt][3] * inv1));
    }
}

// ---------------------------------------------------------------------------
extern "C" void kernel_launch(void* const* d_in, const int* in_sizes, int n_in,
                              void* d_out, int out_size)
{
    const float* x  = (const float*)d_in[0];
    const float* Wq = (const float*)d_in[1];
    const float* bq = (const float*)d_in[2];
    const float* Wk = (const float*)d_in[3];
    const float* bk = (const float*)d_in[4];
    const float* Wv = (const float*)d_in[5];
    const float* bv = (const float*)d_in[6];
    const float* Wo = (const float*)d_in[7];
    const float* bo = (const float*)d_in[8];
    float* out = (float*)d_out;

    cudaFuncSetAttribute(gemm_tf32,
                         cudaFuncAttributeMaxDynamicSharedMemorySize,
                         G_SMEM_BYTES);
    cudaFuncSetAttribute(attn_tc_kernel,
                         cudaFuncAttributeMaxDynamicSharedMemorySize,
                         ATT_SMEM_BYTES);

    // pre-round x + weights: (4M + 4*1M)/4 float4s = 2M threads
    preround_kernel<<<(2 * REG_FLOATS) / 256, 256>>>(x, Wq, Wk, Wv, Wo);

    dim3 gg(CC / GBN, MM / GBM); // (8, 32)

    gemm_tf32<<<gg, 256, G_SMEM_BYTES>>>(bq, nullptr, 0, 0);
    gemm_tf32<<<gg, 256, G_SMEM_BYTES>>>(bk, nullptr, 0, 1);
    gemm_tf32<<<gg, 256, G_SMEM_BYTES>>>(bv, nullptr, 0, 2);

    rope_transpose_kernel<<<(BQ * HH * TT * 16) / 256, 256>>>();

    attn_tc_kernel<<<dim3(TT / 64, BQ * HH), 128, ATT_SMEM_BYTES>>>();

    gemm_tf32<<<gg, 256, G_SMEM_BYTES>>>(bo, out, 1, 3);
}

// round 10
// speedup vs baseline: 1.1975x; 1.0966x over previous
#include <cuda_runtime.h>
#include <cuda_bf16.h>
#include <math.h>

// Problem constants (fixed by the reference)
#define BQ 2
#define TT 2048
#define CC 1024
#define HH 16
#define DD 64
#define MM (BQ*TT)   // 4096 rows

#define REG_FLOATS (CC*CC)
#define L2E 0.8304820237218405f   // log2(10000)/16

// Scratch (device globals: allocation-free rule)
__device__ float g_Q[(size_t)MM*CC];   // [B,H,T,D], rope applied + tf32-rounded
__device__ float g_K[(size_t)MM*CC];   // [B,H,T,D], rope applied + tf32-rounded
__device__ float g_V[(size_t)MM*CC];   // [B,H,T,D], tf32-rounded
__device__ float g_att[(size_t)MM*CC]; // [B,T,C] attention out, tf32-rounded
// Pre-rounded inputs: [ x (4M) | WqT (1M) | WkT | WvT | WoT ]  (weights transposed [n][k])
__device__ float g_pre[(size_t)MM*CC + 4*(size_t)REG_FLOATS];

__device__ __forceinline__ void cp16(void* dst, const void* src) {
    unsigned d = (unsigned)__cvta_generic_to_shared(dst);
    asm volatile("cp.async.cg.shared.global [%0], [%1], 16;\n" :: "r"(d), "l"(src));
}
#define CP_COMMIT() asm volatile("cp.async.commit_group;\n")
#define CP_WAIT(n)  asm volatile("cp.async.wait_group %0;\n" :: "n"(n))

__device__ __forceinline__ void mma_tf32(float c[4], const unsigned a[4],
                                         unsigned b0, unsigned b1) {
    asm volatile(
        "mma.sync.aligned.m16n8k8.row.col.f32.tf32.tf32.f32 "
        "{%0,%1,%2,%3}, {%4,%5,%6,%7}, {%8,%9}, {%0,%1,%2,%3};\n"
        : "+f"(c[0]), "+f"(c[1]), "+f"(c[2]), "+f"(c[3])
        : "r"(a[0]), "r"(a[1]), "r"(a[2]), "r"(a[3]), "r"(b0), "r"(b1));
}
#define CVT_TF32(x) asm volatile("cvt.rna.tf32.f32 %0, %0;\n" : "+r"(x))
#define LDSM4(r0,r1,r2,r3,addr) \
    asm volatile("ldmatrix.sync.aligned.m8n8.x4.shared.b16 {%0,%1,%2,%3}, [%4];\n" \
        : "=r"(r0), "=r"(r1), "=r"(r2), "=r"(r3) : "r"(addr))

__device__ __forceinline__ float round_tf32(float f) {
    unsigned u = __float_as_uint(f);
    CVT_TF32(u);
    return __uint_as_float(u);
}

// ---------------------------------------------------------------------------
// x: round-copy to g_pre. 1 float4/thread.
// ---------------------------------------------------------------------------
__global__ void x_round_kernel(const float* __restrict__ x)
{
    size_t off = ((size_t)blockIdx.x * 256 + threadIdx.x) * 4;
    float4 v = *(const float4*)(x + off);
    v.x = round_tf32(v.x); v.y = round_tf32(v.y);
    v.z = round_tf32(v.z); v.w = round_tf32(v.w);
    *(float4*)(g_pre + off) = v;
}

// ---------------------------------------------------------------------------
// Weights: transpose [k][n] -> [n][k] + round, 32x32 smem tiles.
// ---------------------------------------------------------------------------
__global__ void w_transpose_round(const float* __restrict__ Wq,
                                  const float* __restrict__ Wk,
                                  const float* __restrict__ Wv,
                                  const float* __restrict__ Wo)
{
    __shared__ float tile[32][33];
    int z = blockIdx.z;
    const float* W = (z == 0) ? Wq : (z == 1) ? Wk : (z == 2) ? Wv : Wo;
    float* WT = g_pre + (size_t)MM * CC + (size_t)z * REG_FLOATS;
    int n0 = blockIdx.x * 32, k0 = blockIdx.y * 32;
    int tx = threadIdx.x, ty = threadIdx.y;   // 32 x 8
#pragma unroll
    for (int i = 0; i < 32; i += 8)
        tile[ty + i][tx] = W[(size_t)(k0 + ty + i) * CC + n0 + tx];
    __syncthreads();
#pragma unroll
    for (int i = 0; i < 32; i += 8)
        WT[(size_t)(n0 + ty + i) * CC + k0 + tx] = round_tf32(tile[tx][ty + i]);
}

// ---------------------------------------------------------------------------
// TF32 GEMM, 2-stage pipeline, BOTH operands via ldmatrix (WT is [n][k]).
// mode 0: QKV fused — blockIdx.z picks weight/bias/dst; rope+transpose in
//         epilogue for z<2; V transposed; all outputs tf32-rounded.
// mode 1: final — A=g_att, W=WoT, C=Cext plain + bias.
// ---------------------------------------------------------------------------
#define GBM 128
#define GBN 128
#define GBK 32
#define TS_STRIDE 36                       // both A and B tiles: 128 x 36
#define G_TSZ (128 * TS_STRIDE)            // 4608 floats
#define G_STAGE (2 * G_TSZ)                // 9216 floats
#define G_SMEM_BYTES (2 * G_STAGE * 4)     // 73728 B

__global__ __launch_bounds__(256, 2) void gemm_tf32(
    const float* __restrict__ biasA, const float* __restrict__ biasB,
    const float* __restrict__ biasC, float* __restrict__ Cext, int mode)
{
    const int z = mode ? 3 : blockIdx.z;
    const float* A = mode ? g_att : g_pre;
    const float* W = g_pre + (size_t)MM * CC + (size_t)z * REG_FLOATS;

    extern __shared__ __align__(16) float gsm[];

    const int tid  = threadIdx.x;
    const int lane = tid & 31;
    const int w    = tid >> 5;
    const int wr   = w >> 2;
    const int wc   = w & 3;
    const int bm   = blockIdx.y * GBM;
    const int bn   = blockIdx.x * GBN;

    float c[4][4][4];
#pragma unroll
    for (int mt = 0; mt < 4; mt++)
#pragma unroll
        for (int nt = 0; nt < 4; nt++)
#pragma unroll
            for (int j = 0; j < 4; j++) c[mt][nt][j] = 0.f;

    const int lq = lane >> 3;
    const int lr = lane & 7;
    const int a_row_off = wr * 64 + lr + 8 * (lq & 1);
    const int a_col_off = 4 * (lq >> 1);
    const int b_row = 8 * (lq >> 1) + lr;     // attention-verified B pattern
    const int b_col = 4 * (lq & 1);

    const int NKT = CC / GBK;   // 32

    auto load_tile = [&](int kt, int st) {
        float* As = gsm + st * G_STAGE;
        float* Bs = As + G_TSZ;
#pragma unroll
        for (int i = 0; i < 4; i++) {
            int f = tid + i * 256;
            int row = f >> 3, c4 = f & 7;
            cp16(&As[row * TS_STRIDE + c4 * 4],
                 A + (size_t)(bm + row) * CC + kt * GBK + c4 * 4);
            cp16(&Bs[row * TS_STRIDE + c4 * 4],
                 W + (size_t)(bn + row) * CC + kt * GBK + c4 * 4);
        }
        CP_COMMIT();
    };

    load_tile(0, 0);

    for (int kt = 0; kt < NKT; kt++) {
        if (kt + 1 < NKT) {
            load_tile(kt + 1, (kt + 1) & 1);
            CP_WAIT(1);
        } else {
            CP_WAIT(0);
        }
        __syncthreads();

        float* As = gsm + (kt & 1) * G_STAGE;
        float* Bs = As + G_TSZ;

#pragma unroll
        for (int ks = 0; ks < 4; ks++) {
            unsigned a[4][4];
#pragma unroll
            for (int mt = 0; mt < 4; mt++) {
                unsigned addr = (unsigned)__cvta_generic_to_shared(
                    &As[(a_row_off + mt * 16) * TS_STRIDE + ks * 8 + a_col_off]);
                LDSM4(a[mt][0], a[mt][1], a[mt][2], a[mt][3], addr);
            }
#pragma unroll
            for (int ntp = 0; ntp < 2; ntp++) {
                unsigned b[4];
                unsigned addr = (unsigned)__cvta_generic_to_shared(
                    &Bs[(wc * 32 + ntp * 16 + b_row) * TS_STRIDE + ks * 8 + b_col]);
                LDSM4(b[0], b[1], b[2], b[3], addr);
#pragma unroll
                for (int mt = 0; mt < 4; mt++) {
                    mma_tf32(c[mt][2 * ntp],     a[mt], b[0], b[1]);
                    mma_tf32(c[mt][2 * ntp + 1], a[mt], b[2], b[3]);
                }
            }
        }
        __syncthreads();
    }

    const int fr = lane >> 2;
    const int fc = lane & 3;

    if (mode) {
        // ---- final projection: plain bias add, write out [B,T,C] ----
#pragma unroll
        for (int mt = 0; mt < 4; mt++) {
            int row = bm + wr * 64 + mt * 16 + fr;
#pragma unroll
            for (int nt = 0; nt < 4; nt++) {
                int col = bn + wc * 32 + nt * 8 + 2 * fc;
                float b0 = biasA[col], b1 = biasA[col + 1];
                *(float2*)&Cext[(size_t)row * CC + col] =
                    make_float2(c[mt][nt][0] + b0, c[mt][nt][1] + b1);
                *(float2*)&Cext[(size_t)(row + 8) * CC + col] =
                    make_float2(c[mt][nt][2] + b0, c[mt][nt][3] + b1);
            }
        }
        return;
    }

    // ---- QKV epilogue: bias (+rope for Q/K rot warps), round, transpose ----
    const float* bias = (z == 0) ? biasA : (z == 1) ? biasB : biasC;
    float* dst = (z == 0) ? g_Q : (z == 1) ? g_K : g_V;
    const int hcol  = bn + wc * 32;
    const int h     = hcol >> 6;
    const int dbase = hcol & 63;                 // 0 (rot half) or 32 (pass half)
    const bool dorope = (z < 2) && (dbase == 0);

    float invf[2][2];
    if (dorope) {
#pragma unroll
        for (int nt2 = 0; nt2 < 2; nt2++) {
            int j0 = nt2 * 8 + 2 * fc;
            invf[nt2][0] = exp2f(-(float)j0 * L2E);
            invf[nt2][1] = exp2f(-(float)(j0 + 1) * L2E);
        }
    }

#pragma unroll
    for (int mt = 0; mt < 4; mt++) {
        int grow0 = bm + wr * 64 + mt * 16 + fr;
#pragma unroll
        for (int half = 0; half < 2; half++) {
            int grow = grow0 + half * 8;
            int ri = half * 2;
            int t = grow & (TT - 1);
            int bidx = grow >> 11;
            size_t abase = ((size_t)(bidx * HH + h) * TT + t) * DD;
            if (dorope) {
#pragma unroll
                for (int nt2 = 0; nt2 < 2; nt2++) {
                    int j0 = nt2 * 8 + 2 * fc;
                    int col0 = hcol + j0;
                    float a0 = c[mt][nt2][ri]         + bias[col0];
                    float a1 = c[mt][nt2][ri + 1]     + bias[col0 + 1];
                    float p0 = c[mt][nt2 + 2][ri]     + bias[col0 + 16];
                    float p1 = c[mt][nt2 + 2][ri + 1] + bias[col0 + 17];
                    float s0, cs0, s1, cs1;
                    sincosf((float)t * invf[nt2][0], &s0, &cs0);
                    sincosf((float)t * invf[nt2][1], &s1, &cs1);
                    *(float2*)&dst[abase + j0] = make_float2(
                        round_tf32(a0 * cs0 - p0 * s0),
                        round_tf32(a1 * cs1 - p1 * s1));
                    *(float2*)&dst[abase + j0 + 16] = make_float2(
                        round_tf32(p0 * cs0 + a0 * s0),
                        round_tf32(p1 * cs1 + a1 * s1));
                }
            } else {
#pragma unroll
                for (int nt = 0; nt < 4; nt++) {
                    int col = hcol + nt * 8 + 2 * fc;
                    int d = dbase + nt * 8 + 2 * fc;
                    *(float2*)&dst[abase + d] = make_float2(
                        round_tf32(c[mt][nt][ri]     + bias[col]),
                        round_tf32(c[mt][nt][ri + 1] + bias[col + 1]));
                }
            }
        }
    }
}

// ---------------------------------------------------------------------------
// Flash attention, tf32 mma, 2-stage K/V pipeline (verified R9).
// ---------------------------------------------------------------------------
#define QS_STR 68
#define KS_STR 68
#define VS_STR 72
#define PS_STR 68
#define A_QSZ (64 * QS_STR)
#define A_KSZ (64 * KS_STR)
#define A_VSZ (64 * VS_STR)
#define A_PSZ (64 * PS_STR)
#define A_KVSTAGE (A_KSZ + A_VSZ)
#define ATT_SMEM_BYTES ((A_QSZ + 2 * A_KVSTAGE + A_PSZ) * 4)

__global__ __launch_bounds__(128) void attn_tc_kernel()
{
    extern __shared__ __align__(16) float sm[];
    float* Qs  = sm;
    float* KV0 = Qs + A_QSZ;
    float* KV1 = KV0 + A_KVSTAGE;
    float* Ps  = KV1 + A_KVSTAGE;

    const int bh = blockIdx.y;
    const int qb = blockIdx.x;
    const int tid  = threadIdx.x;
    const int lane = tid & 31;
    const int w    = tid >> 5;

    const float* Qg = g_Q + (size_t)bh * TT * DD + (size_t)qb * 64 * DD;
    const float* Kg = g_K + (size_t)bh * TT * DD;
    const float* Vg = g_V + (size_t)bh * TT * DD;

#pragma unroll
    for (int i = 0; i < 8; i++) {
        int idx = tid + i * 128;
        int r = idx >> 4, c4 = (idx & 15) << 2;
        *(float4*)&Qs[r * QS_STR + c4] = *(const float4*)&Qg[r * DD + c4];
    }

    auto load_kv = [&](int jt, float* stage) {
        float* Ks = stage;
        float* Vs = stage + A_KSZ;
        const float* Kt = Kg + (size_t)jt * 64 * DD;
        const float* Vt = Vg + (size_t)jt * 64 * DD;
#pragma unroll
        for (int i = 0; i < 8; i++) {
            int idx = tid + i * 128;
            int r = idx >> 4, c4 = (idx & 15) << 2;
            cp16(&Ks[r * KS_STR + c4], Kt + r * DD + c4);
            cp16(&Vs[r * VS_STR + c4], Vt + r * DD + c4);
        }
        CP_COMMIT();
    };
    load_kv(0, KV0);

    __syncthreads();

    const int lq = lane >> 3;
    const int lr = lane & 7;
    const int a_row = w * 16 + lr + 8 * (lq & 1);
    const int a_col = 4 * (lq >> 1);
    unsigned qf[8][4];
#pragma unroll
    for (int ks = 0; ks < 8; ks++) {
        unsigned addr = (unsigned)__cvta_generic_to_shared(
            &Qs[a_row * QS_STR + ks * 8 + a_col]);
        LDSM4(qf[ks][0], qf[ks][1], qf[ks][2], qf[ks][3], addr);
    }

    const int b_row = 8 * (lq >> 1) + lr;
    const int b_col = 4 * (lq & 1);

    const int fr = lane >> 2;
    const int fc = lane & 3;
    const int row0_l = w * 16 + fr;
    const int row1_l = row0_l + 8;

    float m0 = -3.0e38f, m1 = -3.0e38f, l0 = 0.f, l1 = 0.f;
    float o[8][4];
#pragma unroll
    for (int nt = 0; nt < 8; nt++)
#pragma unroll
        for (int j = 0; j < 4; j++) o[nt][j] = 0.f;

    for (int jt = 0; jt <= qb; jt++) {
        if (jt < qb) {
            load_kv(jt + 1, (jt & 1) ? KV0 : KV1);
            CP_WAIT(1);
        } else {
            CP_WAIT(0);
        }
        __syncthreads();

        float* Ks = (jt & 1) ? KV1 : KV0;
        float* Vs = Ks + A_KSZ;

        float c[8][4];
#pragma unroll
        for (int nt = 0; nt < 8; nt++)
#pragma unroll
            for (int j = 0; j < 4; j++) c[nt][j] = 0.f;

#pragma unroll
        for (int ks = 0; ks < 8; ks++) {
#pragma unroll
            for (int ntp = 0; ntp < 4; ntp++) {
                unsigned b[4];
                unsigned addr = (unsigned)__cvta_generic_to_shared(
                    &Ks[(ntp * 16 + b_row) * KS_STR + ks * 8 + b_col]);
                LDSM4(b[0], b[1], b[2], b[3], addr);
                mma_tf32(c[2 * ntp],     qf[ks], b[0], b[1]);
                mma_tf32(c[2 * ntp + 1], qf[ks], b[2], b[3]);
            }
        }

        if (jt == qb) {
#pragma unroll
            for (int nt = 0; nt < 8; nt++) {
                int col0 = nt * 8 + 2 * fc, col1 = col0 + 1;
                c[nt][0] = (col0 <= row0_l) ? c[nt][0] * 0.125f : -1.0e30f;
                c[nt][1] = (col1 <= row0_l) ? c[nt][1] * 0.125f : -1.0e30f;
                c[nt][2] = (col0 <= row1_l) ? c[nt][2] * 0.125f : -1.0e30f;
                c[nt][3] = (col1 <= row1_l) ? c[nt][3] * 0.125f : -1.0e30f;
            }
        } else {
#pragma unroll
            for (int nt = 0; nt < 8; nt++)
#pragma unroll
                for (int j = 0; j < 4; j++) c[nt][j] *= 0.125f;
        }

        float mx0 = -3.0e38f, mx1 = -3.0e38f;
#pragma unroll
        for (int nt = 0; nt < 8; nt++) {
            mx0 = fmaxf(mx0, fmaxf(c[nt][0], c[nt][1]));
            mx1 = fmaxf(mx1, fmaxf(c[nt][2], c[nt][3]));
        }
        mx0 = fmaxf(mx0, __shfl_xor_sync(0xffffffffu, mx0, 1));
        mx0 = fmaxf(mx0, __shfl_xor_sync(0xffffffffu, mx0, 2));
        mx1 = fmaxf(mx1, __shfl_xor_sync(0xffffffffu, mx1, 1));
        mx1 = fmaxf(mx1, __shfl_xor_sync(0xffffffffu, mx1, 2));
        float mn0 = fmaxf(m0, mx0), mn1 = fmaxf(m1, mx1);
        float al0 = __expf(m0 - mn0), al1 = __expf(m1 - mn1);

        float rs0 = 0.f, rs1 = 0.f;
#pragma unroll
        for (int nt = 0; nt < 8; nt++) {
            c[nt][0] = __expf(c[nt][0] - mn0);
            c[nt][1] = __expf(c[nt][1] - mn0);
            c[nt][2] = __expf(c[nt][2] - mn1);
            c[nt][3] = __expf(c[nt][3] - mn1);
            rs0 += c[nt][0] + c[nt][1];
            rs1 += c[nt][2] + c[nt][3];
        }
        rs0 += __shfl_xor_sync(0xffffffffu, rs0, 1);
        rs0 += __shfl_xor_sync(0xffffffffu, rs0, 2);
        rs1 += __shfl_xor_sync(0xffffffffu, rs1, 1);
        rs1 += __shfl_xor_sync(0xffffffffu, rs1, 2);
        l0 = l0 * al0 + rs0; m0 = mn0;
        l1 = l1 * al1 + rs1; m1 = mn1;

#pragma unroll
        for (int nt = 0; nt < 8; nt++) {
            o[nt][0] *= al0; o[nt][1] *= al0;
            o[nt][2] *= al1; o[nt][3] *= al1;
            *(float2*)&Ps[row0_l * PS_STR + nt * 8 + 2 * fc] =
                make_float2(c[nt][0], c[nt][1]);
            *(float2*)&Ps[row1_l * PS_STR + nt * 8 + 2 * fc] =
                make_float2(c[nt][2], c[nt][3]);
        }
        __syncwarp();

#pragma unroll
        for (int ks = 0; ks < 8; ks++) {
            unsigned pf[4];
            unsigned addr = (unsigned)__cvta_generic_to_shared(
                &Ps[a_row * PS_STR + ks * 8 + a_col]);
            LDSM4(pf[0], pf[1], pf[2], pf[3], addr);
#pragma unroll
            for (int j = 0; j < 4; j++) CVT_TF32(pf[j]);
            int k = ks * 8 + fc;
#pragma unroll
            for (int nt = 0; nt < 8; nt++) {
                int n = nt * 8 + fr;
                unsigned b0 = __float_as_uint(Vs[k * VS_STR + n]);
                unsigned b1 = __float_as_uint(Vs[(k + 4) * VS_STR + n]);
                mma_tf32(o[nt], pf, b0, b1);
            }
        }
        __syncthreads();
    }

    const int b = bh >> 4, h = bh & 15;
    float inv0 = 1.f / l0, inv1 = 1.f / l1;
    size_t base0 = ((size_t)(b * TT + qb * 64 + row0_l)) * CC + h * DD;
    size_t base1 = ((size_t)(b * TT + qb * 64 + row1_l)) * CC + h * DD;
#pragma unroll
    for (int nt = 0; nt < 8; nt++) {
        int col = nt * 8 + 2 * fc;
        *(float2*)&g_att[base0 + col] =
            make_float2(round_tf32(o[nt][0] * inv0), round_tf32(o[nt][1] * inv0));
        *(float2*)&g_att[base1 + col] =
            make_float2(round_tf32(o[nt][2] * inv1), round_tf32(o[nt][3] * inv1));
    }
}

// ---------------------------------------------------------------------------
extern "C" void kernel_launch(void* const* d_in, const int* in_sizes, int n_in,
                              void* d_out, int out_size)
{
    const float* x  = (const float*)d_in[0];
    const float* Wq = (const float*)d_in[1];
    const float* bq = (const float*)d_in[2];
    const float* Wk = (const float*)d_in[3];
    const float* bk = (const float*)d_in[4];
    const float* Wv = (const float*)d_in[5];
    const float* bv = (const float*)d_in[6];
    const float* Wo = (const float*)d_in[7];
    const float* bo = (const float*)d_in[8];
    float* out = (float*)d_out;

    cudaFuncSetAttribute(gemm_tf32,
                         cudaFuncAttributeMaxDynamicSharedMemorySize,
                         G_SMEM_BYTES);
    cudaFuncSetAttribute(attn_tc_kernel,
                         cudaFuncAttributeMaxDynamicSharedMemorySize,
                         ATT_SMEM_BYTES);

    x_round_kernel<<<(MM * CC) / (4 * 256), 256>>>(x);
    w_transpose_round<<<dim3(32, 32, 4), dim3(32, 8)>>>(Wq, Wk, Wv, Wo);

    // fused QKV (rope+transpose in epilogue), one launch
    gemm_tf32<<<dim3(CC / GBN, MM / GBM, 3), 256, G_SMEM_BYTES>>>(
        bq, bk, bv, nullptr, 0);

    attn_tc_kernel<<<dim3(TT / 64, BQ * HH), 128, ATT_SMEM_BYTES>>>();

    gemm_tf32<<<dim3(CC / GBN, MM / GBM, 1), 256, G_SMEM_BYTES>>>(
        bo, nullptr, nullptr, out, 1);
}